// round 12
// baseline (speedup 1.0000x reference)
#include <cuda_runtime.h>

#define TT 64
#define FULL 0xffffffffu

__device__ __forceinline__ float sx(float v, int m) { return __shfl_xor_sync(FULL, v, m); }
__device__ __forceinline__ float tanhap(float v) {
    float r; asm("tanh.approx.f32 %0, %1;" : "=f"(r) : "f"(v)); return r;
}
__device__ __forceinline__ float pick4(const float a[4], int j) {
    float xv = (j & 2) ? a[2] : a[0];
    float yv = (j & 2) ? a[3] : a[1];
    return (j & 1) ? yv : xv;
}
// basis coefficient: factor type p (0: cos(alpha), 1: sin(alpha)), basis bit b
// (0 -> cY, 1 -> sY), rotation consts cg=cos(W0), sg=sin(W0).
__device__ __forceinline__ float fco(int p, int b, float cg, float sg) {
    return p ? (b ? cg : sg) : (b ? -sg : cg);
}

__global__ void __launch_bounds__(64, 1)
qlstmcf(const float* __restrict__ x,
        const float* __restrict__ w_in,  const float* __restrict__ b_in,
        const float* __restrict__ w_out, const float* __restrict__ b_out,
        const float* __restrict__ wq_f,  const float* __restrict__ wq_i,
        const float* __restrict__ wq_u,  const float* __restrict__ wq_o,
        const float* __restrict__ w_fc,  const float* __restrict__ b_fc,
        float* __restrict__ out, int B)
{
    const int lane = threadIdx.x & 31;
    const int wib  = threadIdx.x >> 5;
    const int sub  = lane & 7;            // own h/c component
    const int b8   = lane & ~7;
    const int slot = wib * 4 + (lane >> 3);
    int e = blockIdx.x * 8 + slot;
    const bool ok = (e < B);
    if (!ok) e = B - 1;

    __shared__ float sxp[8][TT * 4 + 4];  // +4 pad: slot stride 260 avoids bank clash

    // ---- prepass: x-part of angles (incl. b_in), full angle scale ----
    {
        const float* xe = x + (long)e * TT * 32;
        float acc[8][4];
#pragma unroll
        for (int i = 0; i < 8; ++i)
#pragma unroll
            for (int w = 0; w < 4; ++w) acc[i][w] = 0.f;
#pragma unroll
        for (int c = 0; c < 8; ++c) {
            float4 wv[4];
#pragma unroll
            for (int w = 0; w < 4; ++w)
                wv[w] = *reinterpret_cast<const float4*>(&w_in[w * 40 + 8 + 4 * c]);
#pragma unroll
            for (int i = 0; i < 8; ++i) {
                float4 xv = *reinterpret_cast<const float4*>(&xe[(8 * sub + i) * 32 + 4 * c]);
#pragma unroll
                for (int w = 0; w < 4; ++w) {
                    acc[i][w] = fmaf(xv.x, wv[w].x, acc[i][w]);
                    acc[i][w] = fmaf(xv.y, wv[w].y, acc[i][w]);
                    acc[i][w] = fmaf(xv.z, wv[w].z, acc[i][w]);
                    acc[i][w] = fmaf(xv.w, wv[w].w, acc[i][w]);
                }
            }
        }
#pragma unroll
        for (int i = 0; i < 8; ++i)
#pragma unroll
            for (int w = 0; w < 4; ++w)
                sxp[slot][(8 * sub + i) * 4 + w] = acc[i][w] + __ldg(&b_in[w]);
    }
    __syncthreads();

    // ---- per-gate closed-form coefficient vectors ----
    float Whl[4];
#pragma unroll
    for (int w = 0; w < 4; ++w) Whl[w] = __ldg(&w_in[w * 40 + sub]);

    float V013[4][8], V023[4][8], V13[4][4], V02[4][4], boA[4];
#pragma unroll
    for (int g = 0; g < 4; ++g) {
        const float* wq = (g == 0) ? wq_f : (g == 1) ? wq_i : (g == 2) ? wq_u : wq_o;
        float cb[4], sb[4], cg_[4], sg_[4];
#pragma unroll
        for (int w = 0; w < 4; ++w) {
            float bv = __ldg(&wq[4 + w]); cb[w] = cosf(bv); sb[w] = sinf(bv);
            float cv = __ldg(&wq[w]);     cg_[w] = cosf(cv); sg_[w] = sinf(cv);
        }
        const float asc = (g == 2) ? 1.f : 0.5f;
        float Wo[4];
#pragma unroll
        for (int w = 0; w < 4; ++w) Wo[w] = asc * __ldg(&w_out[sub * 4 + w]);
        boA[g] = asc * __ldg(&b_out[sub]);

        // E0: wires {0,1,3}; patterns (bit0->w0, bit1->w1, bit2->w3)
        {
            const int   p0[4] = {0, 7, 6, 1};
            const float K0[4] = {cb[1]*cb[2]*cb[3], cb[1]*cb[2]*sb[3],
                                 sb[1]*sb[2]*cb[3], sb[1]*sb[2]*sb[3]};
#pragma unroll
            for (int b = 0; b < 8; ++b) {
                float s = 0.f;
#pragma unroll
                for (int t = 0; t < 4; ++t)
                    s += K0[t] * fco(p0[t] & 1, b & 1, cg_[0], sg_[0])
                               * fco((p0[t] >> 1) & 1, (b >> 1) & 1, cg_[1], sg_[1])
                               * fco((p0[t] >> 2) & 1, (b >> 2) & 1, cg_[3], sg_[3]);
                V013[g][b] = Wo[0] * s;
            }
        }
        // E1: wires {0,2,3}
        {
            const int   p1[2] = {0, 3};
            const float K1[2] = {cb[0]*cb[1], sb[0]*sb[1]};
#pragma unroll
            for (int b = 0; b < 8; ++b) {
                float s = 0.f;
#pragma unroll
                for (int t = 0; t < 2; ++t)
                    s += K1[t] * fco(p1[t] & 1, b & 1, cg_[0], sg_[0])
                               * fco((p1[t] >> 1) & 1, (b >> 1) & 1, cg_[2], sg_[2])
                               * fco((p1[t] >> 2) & 1, (b >> 2) & 1, cg_[3], sg_[3]);
                V023[g][b] = Wo[1] * s;
            }
        }
        // E2: wires {1,3}
        {
            const int   p2[2] = {0, 3};
            const float K2[2] = {cb[0]*cb[1]*cb[2], cb[0]*sb[1]*sb[2]};
#pragma unroll
            for (int b = 0; b < 4; ++b) {
                float s = 0.f;
#pragma unroll
                for (int t = 0; t < 2; ++t)
                    s += K2[t] * fco(p2[t] & 1, b & 1, cg_[1], sg_[1])
                               * fco((p2[t] >> 1) & 1, (b >> 1) & 1, cg_[3], sg_[3]);
                V13[g][b] = Wo[2] * s;
            }
        }
        // E3: wires {0,2}
        {
            const int   p3[4] = {0, 3, 2, 1};
            const float K3[4] = {cb[0]*cb[1]*cb[2]*cb[3], sb[0]*sb[1]*cb[2]*cb[3],
                                 sb[0]*cb[1]*sb[2]*sb[3], cb[0]*sb[1]*sb[2]*sb[3]};
#pragma unroll
            for (int b = 0; b < 4; ++b) {
                float s = 0.f;
#pragma unroll
                for (int t = 0; t < 4; ++t)
                    s += K3[t] * fco(p3[t] & 1, b & 1, cg_[0], sg_[0])
                               * fco((p3[t] >> 1) & 1, (b >> 1) & 1, cg_[2], sg_[2]);
                V02[g][b] = Wo[3] * s;
            }
        }
    }

    float cc = 0.f, h = 0.f;

#pragma unroll 1
    for (int t = 0; t < TT; ++t) {
        // S1: angle transpose-reduce (one stage)
        float pw[4];
#pragma unroll
        for (int w = 0; w < 4; ++w) pw[w] = h * Whl[w];
        float red = pick4(pw, sub & 3);
#pragma unroll
        for (int m = 1; m < 8; ++m)
            red += sx(pick4(pw, (sub ^ m) & 3), m);
        float ang = red + sxp[slot][t * 4 + (sub & 3)];

        // S2: own sincos; share 4 wires
        float mys, myc;
        __sincosf(ang, &mys, &myc);
        float cY[4], sY[4];
#pragma unroll
        for (int w = 0; w < 4; ++w) {
            cY[w] = __shfl_sync(FULL, myc, b8 | w);
            sY[w] = __shfl_sync(FULL, mys, b8 | w);
        }

        // shared product basis
        float p01[4] = {cY[0]*cY[1], sY[0]*cY[1], cY[0]*sY[1], sY[0]*sY[1]};
        float p02[4] = {cY[0]*cY[2], sY[0]*cY[2], cY[0]*sY[2], sY[0]*sY[2]};
        float p13[4] = {cY[1]*cY[3], sY[1]*cY[3], cY[1]*sY[3], sY[1]*sY[3]};
        float P013[8], P023[8];
#pragma unroll
        for (int b = 0; b < 8; ++b) {
            float t3 = (b & 4) ? sY[3] : cY[3];
            P013[b] = p01[b & 3] * t3;
            P023[b] = p02[b & 3] * t3;
        }

        // all 4 gate activations, fully local
        float act[4];
#pragma unroll
        for (int g = 0; g < 4; ++g) {
            float gv = boA[g];
#pragma unroll
            for (int b = 0; b < 8; ++b) gv = fmaf(V013[g][b], P013[b], gv);
#pragma unroll
            for (int b = 0; b < 8; ++b) gv = fmaf(V023[g][b], P023[b], gv);
#pragma unroll
            for (int b = 0; b < 4; ++b) gv = fmaf(V13[g][b], p13[b], gv);
#pragma unroll
            for (int b = 0; b < 4; ++b) gv = fmaf(V02[g][b], p02[b], gv);
            act[g] = (g == 2) ? tanhap(gv) : fmaf(0.5f, tanhap(gv), 0.5f);
        }

        // LSTM update (lane-local)
        cc = fmaf(act[0], cc, act[1] * act[2]);
        h = act[3] * tanhap(cc);
    }

    // ---- final projection ----
    float p = h * __ldg(&w_fc[sub]);
    p += sx(p, 1);
    p += sx(p, 2);
    p += sx(p, 4);
    if (sub == 0 && ok) out[e] = p + __ldg(&b_fc[0]);
}

extern "C" void kernel_launch(void* const* d_in, const int* in_sizes, int n_in,
                              void* d_out, int out_size) {
    const float* x     = (const float*)d_in[0];
    const float* w_in  = (const float*)d_in[1];
    const float* b_in  = (const float*)d_in[2];
    const float* w_out = (const float*)d_in[3];
    const float* b_out = (const float*)d_in[4];
    const float* wq_f  = (const float*)d_in[5];
    const float* wq_i  = (const float*)d_in[6];
    const float* wq_u  = (const float*)d_in[7];
    const float* wq_o  = (const float*)d_in[8];
    const float* w_fc  = (const float*)d_in[9];
    const float* b_fc  = (const float*)d_in[10];

    int B = in_sizes[0] / (TT * 32);
    int blocks = (B + 7) / 8;              // 8 elements per 64-thread block
    qlstmcf<<<blocks, 64>>>(x, w_in, b_in, w_out, b_out,
                            wq_f, wq_i, wq_u, wq_o, w_fc, b_fc,
                            (float*)d_out, B);
}

// round 13
// speedup vs baseline: 1.2653x; 1.2653x over previous
#include <cuda_runtime.h>

#define TT 64
#define FULL 0xffffffffu

__device__ __forceinline__ float sx(float v, int m) { return __shfl_xor_sync(FULL, v, m); }
__device__ __forceinline__ float tanhap(float v) {
    float r; asm("tanh.approx.f32 %0, %1;" : "=f"(r) : "f"(v)); return r;
}
__device__ __forceinline__ float pick4(const float a[4], int j) {
    float xv = (j & 2) ? a[2] : a[0];
    float yv = (j & 2) ? a[3] : a[1];
    return (j & 1) ? yv : xv;
}
// basis coefficient: factor p (0:cos(alpha),1:sin(alpha)), basis bit b (0->cY,1->sY)
__device__ __forceinline__ float fco(int p, int b, float cg, float sg) {
    return p ? (b ? cg : sg) : (b ? -sg : cg);
}

// One warp = one element. lane = g*8 + sub (sub = h/c component).
__global__ void __launch_bounds__(128)
qlstmcf32(const float* __restrict__ x,
          const float* __restrict__ w_in,  const float* __restrict__ b_in,
          const float* __restrict__ w_out, const float* __restrict__ b_out,
          const float* __restrict__ wq_f,  const float* __restrict__ wq_i,
          const float* __restrict__ wq_u,  const float* __restrict__ wq_o,
          const float* __restrict__ w_fc,  const float* __restrict__ b_fc,
          float* __restrict__ out, int B)
{
    const int lane = threadIdx.x & 31;
    const int wib  = threadIdx.x >> 5;
    const int g    = lane >> 3;
    const int sub  = lane & 7;
    const int b8   = lane & ~7;
    int e = blockIdx.x * 4 + wib;
    const bool ok = (e < B);
    if (!ok) e = B - 1;

    __shared__ float sxp[4][TT * 4 + 4];

    // ---- prepass: x-part of angles (incl. b_in); 2 timesteps per lane ----
    {
        const float* xe = x + (long)e * TT * 32;
        const int t0i = lane * 2;
        float acc[2][4];
#pragma unroll
        for (int i = 0; i < 2; ++i)
#pragma unroll
            for (int w = 0; w < 4; ++w) acc[i][w] = 0.f;
#pragma unroll
        for (int c = 0; c < 8; ++c) {
            float4 wv[4];
#pragma unroll
            for (int w = 0; w < 4; ++w)
                wv[w] = *reinterpret_cast<const float4*>(&w_in[w * 40 + 8 + 4 * c]);
            float4 xv0 = *reinterpret_cast<const float4*>(&xe[t0i * 32 + 4 * c]);
            float4 xv1 = *reinterpret_cast<const float4*>(&xe[(t0i + 1) * 32 + 4 * c]);
#pragma unroll
            for (int w = 0; w < 4; ++w) {
                acc[0][w] = fmaf(xv0.x, wv[w].x, acc[0][w]);
                acc[0][w] = fmaf(xv0.y, wv[w].y, acc[0][w]);
                acc[0][w] = fmaf(xv0.z, wv[w].z, acc[0][w]);
                acc[0][w] = fmaf(xv0.w, wv[w].w, acc[0][w]);
                acc[1][w] = fmaf(xv1.x, wv[w].x, acc[1][w]);
                acc[1][w] = fmaf(xv1.y, wv[w].y, acc[1][w]);
                acc[1][w] = fmaf(xv1.z, wv[w].z, acc[1][w]);
                acc[1][w] = fmaf(xv1.w, wv[w].w, acc[1][w]);
            }
        }
#pragma unroll
        for (int i = 0; i < 2; ++i)
#pragma unroll
            for (int w = 0; w < 4; ++w)
                sxp[wib][(t0i + i) * 4 + w] = acc[i][w] + __ldg(&b_in[w]);
    }
    __syncwarp();

    // ---- own-gate closed-form coefficient vectors (R11 formulas, passed) ----
    float Whl[4];
#pragma unroll
    for (int w = 0; w < 4; ++w) Whl[w] = __ldg(&w_in[w * 40 + sub]);

    const float* wq = (g == 0) ? wq_f : (g == 1) ? wq_i : (g == 2) ? wq_u : wq_o;
    float cb[4], sb[4], cg_[4], sg_[4];
#pragma unroll
    for (int w = 0; w < 4; ++w) {
        float bv = __ldg(&wq[4 + w]); cb[w] = cosf(bv); sb[w] = sinf(bv);
        float cv = __ldg(&wq[w]);     cg_[w] = cosf(cv); sg_[w] = sinf(cv);
    }
    const float asc = (g == 2) ? 1.f : 0.5f;
    float Wo[4];
#pragma unroll
    for (int w = 0; w < 4; ++w) Wo[w] = asc * __ldg(&w_out[sub * 4 + w]);
    const float bo = asc * __ldg(&b_out[sub]);

    float V013[8], V023[8], V13[4], V02[4];
    {   // E0: wires {0,1,3}
        const int   p0[4] = {0, 7, 6, 1};
        const float K0[4] = {cb[1]*cb[2]*cb[3], cb[1]*cb[2]*sb[3],
                             sb[1]*sb[2]*cb[3], sb[1]*sb[2]*sb[3]};
#pragma unroll
        for (int b = 0; b < 8; ++b) {
            float s = 0.f;
#pragma unroll
            for (int t = 0; t < 4; ++t)
                s += K0[t] * fco(p0[t] & 1, b & 1, cg_[0], sg_[0])
                           * fco((p0[t] >> 1) & 1, (b >> 1) & 1, cg_[1], sg_[1])
                           * fco((p0[t] >> 2) & 1, (b >> 2) & 1, cg_[3], sg_[3]);
            V013[b] = Wo[0] * s;
        }
    }
    {   // E1: wires {0,2,3}
        const int   p1[2] = {0, 3};
        const float K1[2] = {cb[0]*cb[1], sb[0]*sb[1]};
#pragma unroll
        for (int b = 0; b < 8; ++b) {
            float s = 0.f;
#pragma unroll
            for (int t = 0; t < 2; ++t)
                s += K1[t] * fco(p1[t] & 1, b & 1, cg_[0], sg_[0])
                           * fco((p1[t] >> 1) & 1, (b >> 1) & 1, cg_[2], sg_[2])
                           * fco((p1[t] >> 2) & 1, (b >> 2) & 1, cg_[3], sg_[3]);
            V023[b] = Wo[1] * s;
        }
    }
    {   // E2: wires {1,3}
        const int   p2[2] = {0, 3};
        const float K2[2] = {cb[0]*cb[1]*cb[2], cb[0]*sb[1]*sb[2]};
#pragma unroll
        for (int b = 0; b < 4; ++b) {
            float s = 0.f;
#pragma unroll
            for (int t = 0; t < 2; ++t)
                s += K2[t] * fco(p2[t] & 1, b & 1, cg_[1], sg_[1])
                           * fco((p2[t] >> 1) & 1, (b >> 1) & 1, cg_[3], sg_[3]);
            V13[b] = Wo[2] * s;
        }
    }
    {   // E3: wires {0,2}
        const int   p3[4] = {0, 3, 2, 1};
        const float K3[4] = {cb[0]*cb[1]*cb[2]*cb[3], sb[0]*sb[1]*cb[2]*cb[3],
                             sb[0]*cb[1]*sb[2]*sb[3], cb[0]*sb[1]*sb[2]*sb[3]};
#pragma unroll
        for (int b = 0; b < 4; ++b) {
            float s = 0.f;
#pragma unroll
            for (int t = 0; t < 4; ++t)
                s += K3[t] * fco(p3[t] & 1, b & 1, cg_[0], sg_[0])
                           * fco((p3[t] >> 1) & 1, (b >> 1) & 1, cg_[2], sg_[2]);
            V02[b] = Wo[3] * s;
        }
    }

    float cc = 0.f, h = 0.f;

#pragma unroll 1
    for (int t = 0; t < TT; ++t) {
        // S1: angle transpose-reduce within 8-lane group (one stage)
        float pw[4];
#pragma unroll
        for (int w = 0; w < 4; ++w) pw[w] = h * Whl[w];
        float red = pick4(pw, sub & 3);
#pragma unroll
        for (int m = 1; m < 8; ++m)
            red += sx(pick4(pw, (sub ^ m) & 3), m);
        float ang = red + sxp[wib][t * 4 + (sub & 3)];

        // S2: own sincos; share 4 wires
        float mys, myc;
        __sincosf(ang, &mys, &myc);
        float cY[4], sY[4];
#pragma unroll
        for (int w = 0; w < 4; ++w) {
            cY[w] = __shfl_sync(FULL, myc, b8 | w);
            sY[w] = __shfl_sync(FULL, mys, b8 | w);
        }

        // shared product basis
        float p01[4] = {cY[0]*cY[1], sY[0]*cY[1], cY[0]*sY[1], sY[0]*sY[1]};
        float p02[4] = {cY[0]*cY[2], sY[0]*cY[2], cY[0]*sY[2], sY[0]*sY[2]};
        float p13[4] = {cY[1]*cY[3], sY[1]*cY[3], cY[1]*sY[3], sY[1]*sY[3]};
        float P013[8], P023[8];
#pragma unroll
        for (int b = 0; b < 8; ++b) {
            float t3 = (b & 4) ? sY[3] : cY[3];
            P013[b] = p01[b & 3] * t3;
            P023[b] = p02[b & 3] * t3;
        }

        // own-gate dot, 4 parallel accumulators (tree)
        float a0 = bo, a1 = 0.f, a2 = 0.f, a3 = 0.f;
#pragma unroll
        for (int b = 0; b < 8; b += 4) {
            a0 = fmaf(V013[b],     P013[b],     a0);
            a1 = fmaf(V013[b + 1], P013[b + 1], a1);
            a2 = fmaf(V013[b + 2], P013[b + 2], a2);
            a3 = fmaf(V013[b + 3], P013[b + 3], a3);
        }
#pragma unroll
        for (int b = 0; b < 8; b += 4) {
            a0 = fmaf(V023[b],     P023[b],     a0);
            a1 = fmaf(V023[b + 1], P023[b + 1], a1);
            a2 = fmaf(V023[b + 2], P023[b + 2], a2);
            a3 = fmaf(V023[b + 3], P023[b + 3], a3);
        }
        a0 = fmaf(V13[0], p13[0], a0); a1 = fmaf(V13[1], p13[1], a1);
        a2 = fmaf(V13[2], p13[2], a2); a3 = fmaf(V13[3], p13[3], a3);
        a0 = fmaf(V02[0], p02[0], a0); a1 = fmaf(V02[1], p02[1], a1);
        a2 = fmaf(V02[2], p02[2], a2); a3 = fmaf(V02[3], p02[3], a3);
        float gv = (a0 + a1) + (a2 + a3);

        float act = (g == 2) ? tanhap(gv) : fmaf(0.5f, tanhap(gv), 0.5f);

        // S3: gather 4 gates for own comp; lane-local cell update
        float fv = __shfl_sync(FULL, act, sub);
        float iv = __shfl_sync(FULL, act, sub + 8);
        float uv = __shfl_sync(FULL, act, sub + 16);
        float ov = __shfl_sync(FULL, act, sub + 24);
        cc = fmaf(fv, cc, iv * uv);
        h = ov * tanhap(cc);
    }

    // ---- final projection over 8 comps ----
    float p = h * __ldg(&w_fc[sub]);
    p += sx(p, 1);
    p += sx(p, 2);
    p += sx(p, 4);
    if (lane == 0 && ok) out[e] = p + __ldg(&b_fc[0]);
}

extern "C" void kernel_launch(void* const* d_in, const int* in_sizes, int n_in,
                              void* d_out, int out_size) {
    const float* x     = (const float*)d_in[0];
    const float* w_in  = (const float*)d_in[1];
    const float* b_in  = (const float*)d_in[2];
    const float* w_out = (const float*)d_in[3];
    const float* b_out = (const float*)d_in[4];
    const float* wq_f  = (const float*)d_in[5];
    const float* wq_i  = (const float*)d_in[6];
    const float* wq_u  = (const float*)d_in[7];
    const float* wq_o  = (const float*)d_in[8];
    const float* w_fc  = (const float*)d_in[9];
    const float* b_fc  = (const float*)d_in[10];

    int B = in_sizes[0] / (TT * 32);
    int blocks = (B + 3) / 4;              // 4 elements (warps) per block
    qlstmcf32<<<blocks, 128>>>(x, w_in, b_in, w_out, b_out,
                               wq_f, wq_i, wq_u, wq_o, w_fc, b_fc,
                               (float*)d_out, B);
}

// round 14
// speedup vs baseline: 1.3720x; 1.0843x over previous
#include <cuda_runtime.h>

#define TT 64
#define FULL 0xffffffffu

__device__ __forceinline__ float sx(float v, int m) { return __shfl_xor_sync(FULL, v, m); }
__device__ __forceinline__ float tanhap(float v) {
    float r; asm("tanh.approx.f32 %0, %1;" : "=f"(r) : "f"(v)); return r;
}
// basis coefficient: factor p (0:cos(alpha),1:sin(alpha)), basis bit b (0->cY,1->sY)
__device__ __forceinline__ float fco(int p, int b, float cg, float sg) {
    return p ? (b ? cg : sg) : (b ? -sg : cg);
}

// One warp = one element. lane = g*8 + sub (sub = h/c component).
__global__ void __launch_bounds__(256)
qlstmcf32b(const float* __restrict__ x,
           const float* __restrict__ w_in,  const float* __restrict__ b_in,
           const float* __restrict__ w_out, const float* __restrict__ b_out,
           const float* __restrict__ wq_f,  const float* __restrict__ wq_i,
           const float* __restrict__ wq_u,  const float* __restrict__ wq_o,
           const float* __restrict__ w_fc,  const float* __restrict__ b_fc,
           float* __restrict__ out, int B)
{
    const int lane = threadIdx.x & 31;
    const int wib  = threadIdx.x >> 5;     // warp in block (0..7)
    const int g    = lane >> 3;
    const int sub  = lane & 7;
    const int b8   = lane & ~7;
    int e = blockIdx.x * 8 + wib;
    const bool ok = (e < B);
    if (!ok) e = B - 1;

    __shared__ float sxp[8][TT * 4 + 4];

    // ---- prepass: x-part of angles (incl. b_in); 2 timesteps per lane ----
    {
        const float* xe = x + (long)e * TT * 32;
        const int t0i = lane * 2;
        float acc[2][4];
#pragma unroll
        for (int i = 0; i < 2; ++i)
#pragma unroll
            for (int w = 0; w < 4; ++w) acc[i][w] = 0.f;
#pragma unroll
        for (int c = 0; c < 8; ++c) {
            float4 wv[4];
#pragma unroll
            for (int w = 0; w < 4; ++w)
                wv[w] = *reinterpret_cast<const float4*>(&w_in[w * 40 + 8 + 4 * c]);
            float4 xv0 = *reinterpret_cast<const float4*>(&xe[t0i * 32 + 4 * c]);
            float4 xv1 = *reinterpret_cast<const float4*>(&xe[(t0i + 1) * 32 + 4 * c]);
#pragma unroll
            for (int w = 0; w < 4; ++w) {
                acc[0][w] = fmaf(xv0.x, wv[w].x, acc[0][w]);
                acc[0][w] = fmaf(xv0.y, wv[w].y, acc[0][w]);
                acc[0][w] = fmaf(xv0.z, wv[w].z, acc[0][w]);
                acc[0][w] = fmaf(xv0.w, wv[w].w, acc[0][w]);
                acc[1][w] = fmaf(xv1.x, wv[w].x, acc[1][w]);
                acc[1][w] = fmaf(xv1.y, wv[w].y, acc[1][w]);
                acc[1][w] = fmaf(xv1.z, wv[w].z, acc[1][w]);
                acc[1][w] = fmaf(xv1.w, wv[w].w, acc[1][w]);
            }
        }
#pragma unroll
        for (int i = 0; i < 2; ++i)
#pragma unroll
            for (int w = 0; w < 4; ++w)
                sxp[wib][(t0i + i) * 4 + w] = acc[i][w] + __ldg(&b_in[w]);
    }
    __syncwarp();

    // ---- permuted h-projection weights: Whp[m] = W[(sub^m)&3][sub] ----
    float Whp[8];
#pragma unroll
    for (int m = 0; m < 8; ++m)
        Whp[m] = __ldg(&w_in[((sub ^ m) & 3) * 40 + sub]);

    // ---- own-gate closed-form coefficient vectors (R11/R12, validated) ----
    const float* wq = (g == 0) ? wq_f : (g == 1) ? wq_i : (g == 2) ? wq_u : wq_o;
    float cb[4], sb[4], cg_[4], sg_[4];
#pragma unroll
    for (int w = 0; w < 4; ++w) {
        float bv = __ldg(&wq[4 + w]); cb[w] = cosf(bv); sb[w] = sinf(bv);
        float cv = __ldg(&wq[w]);     cg_[w] = cosf(cv); sg_[w] = sinf(cv);
    }
    const float asc = (g == 2) ? 1.f : 0.5f;
    float Wo[4];
#pragma unroll
    for (int w = 0; w < 4; ++w) Wo[w] = asc * __ldg(&w_out[sub * 4 + w]);
    const float bo = asc * __ldg(&b_out[sub]);

    float V013[8], V023[8], V13[4], V02[4];
    {   // E0: wires {0,1,3}
        const int   p0[4] = {0, 7, 6, 1};
        const float K0[4] = {cb[1]*cb[2]*cb[3], cb[1]*cb[2]*sb[3],
                             sb[1]*sb[2]*cb[3], sb[1]*sb[2]*sb[3]};
#pragma unroll
        for (int b = 0; b < 8; ++b) {
            float s = 0.f;
#pragma unroll
            for (int t = 0; t < 4; ++t)
                s += K0[t] * fco(p0[t] & 1, b & 1, cg_[0], sg_[0])
                           * fco((p0[t] >> 1) & 1, (b >> 1) & 1, cg_[1], sg_[1])
                           * fco((p0[t] >> 2) & 1, (b >> 2) & 1, cg_[3], sg_[3]);
            V013[b] = Wo[0] * s;
        }
    }
    {   // E1: wires {0,2,3}
        const int   p1[2] = {0, 3};
        const float K1[2] = {cb[0]*cb[1], sb[0]*sb[1]};
#pragma unroll
        for (int b = 0; b < 8; ++b) {
            float s = 0.f;
#pragma unroll
            for (int t = 0; t < 2; ++t)
                s += K1[t] * fco(p1[t] & 1, b & 1, cg_[0], sg_[0])
                           * fco((p1[t] >> 1) & 1, (b >> 1) & 1, cg_[2], sg_[2])
                           * fco((p1[t] >> 2) & 1, (b >> 2) & 1, cg_[3], sg_[3]);
            V023[b] = Wo[1] * s;
        }
    }
    {   // E2: wires {1,3}
        const int   p2[2] = {0, 3};
        const float K2[2] = {cb[0]*cb[1]*cb[2], cb[0]*sb[1]*sb[2]};
#pragma unroll
        for (int b = 0; b < 4; ++b) {
            float s = 0.f;
#pragma unroll
            for (int t = 0; t < 2; ++t)
                s += K2[t] * fco(p2[t] & 1, b & 1, cg_[1], sg_[1])
                           * fco((p2[t] >> 1) & 1, (b >> 1) & 1, cg_[3], sg_[3]);
            V13[b] = Wo[2] * s;
        }
    }
    {   // E3: wires {0,2}
        const int   p3[4] = {0, 3, 2, 1};
        const float K3[4] = {cb[0]*cb[1]*cb[2]*cb[3], sb[0]*sb[1]*cb[2]*cb[3],
                             sb[0]*cb[1]*sb[2]*sb[3], cb[0]*sb[1]*sb[2]*sb[3]};
#pragma unroll
        for (int b = 0; b < 4; ++b) {
            float s = 0.f;
#pragma unroll
            for (int t = 0; t < 4; ++t)
                s += K3[t] * fco(p3[t] & 1, b & 1, cg_[0], sg_[0])
                           * fco((p3[t] >> 1) & 1, (b >> 1) & 1, cg_[2], sg_[2]);
            V02[b] = Wo[3] * s;
        }
    }

    float cc = 0.f, h = 0.f;

#pragma unroll 1
    for (int t = 0; t < TT; ++t) {
        // S1: angle transpose-reduce (one stage; no SELs — Whp pre-permuted)
        float xval = sxp[wib][t * 4 + (sub & 3)];
        float red = fmaf(h, Whp[0], xval);
        red += sx(h * Whp[1], 1);
        red += sx(h * Whp[2], 2);
        red += sx(h * Whp[3], 3);
        red += sx(h * Whp[4], 4);
        red += sx(h * Whp[5], 5);
        red += sx(h * Whp[6], 6);
        red += sx(h * Whp[7], 7);

        // S2: own sincos; share 4 wires
        float mys, myc;
        __sincosf(red, &mys, &myc);
        float cY[4], sY[4];
#pragma unroll
        for (int w = 0; w < 4; ++w) {
            cY[w] = __shfl_sync(FULL, myc, b8 | w);
            sY[w] = __shfl_sync(FULL, mys, b8 | w);
        }

        // compact basis
        float p01[4] = {cY[0]*cY[1], sY[0]*cY[1], cY[0]*sY[1], sY[0]*sY[1]};
        float p02[4] = {cY[0]*cY[2], sY[0]*cY[2], cY[0]*sY[2], sY[0]*sY[2]};

        // own-gate dot with Y3 factored out: gv = bo + V02.p02 + cY3*A + sY3*B
        float a0 = V013[0] * p01[0], a1 = V013[1] * p01[1];
        a0 = fmaf(V013[2], p01[2], a0); a1 = fmaf(V013[3], p01[3], a1);
        a0 = fmaf(V023[0], p02[0], a0); a1 = fmaf(V023[1], p02[1], a1);
        a0 = fmaf(V023[2], p02[2], a0); a1 = fmaf(V023[3], p02[3], a1);
        a0 = fmaf(V13[0], cY[1], a0);   a1 = fmaf(V13[1], sY[1], a1);
        float A = a0 + a1;

        float b0 = V013[4] * p01[0], b1 = V013[5] * p01[1];
        b0 = fmaf(V013[6], p01[2], b0); b1 = fmaf(V013[7], p01[3], b1);
        b0 = fmaf(V023[4], p02[0], b0); b1 = fmaf(V023[5], p02[1], b1);
        b0 = fmaf(V023[6], p02[2], b0); b1 = fmaf(V023[7], p02[3], b1);
        b0 = fmaf(V13[2], cY[1], b0);   b1 = fmaf(V13[3], sY[1], b1);
        float Bv = b0 + b1;

        float g0 = fmaf(V02[0], p02[0], bo);
        float g1 = V02[1] * p02[1];
        g0 = fmaf(V02[2], p02[2], g0);
        g1 = fmaf(V02[3], p02[3], g1);
        float gv = fmaf(cY[3], A, fmaf(sY[3], Bv, g0 + g1));

        float act = (g == 2) ? tanhap(gv) : fmaf(0.5f, tanhap(gv), 0.5f);

        // S3: gather 4 gates for own comp; lane-local cell update
        float fv = __shfl_sync(FULL, act, sub);
        float iv = __shfl_sync(FULL, act, sub + 8);
        float uv = __shfl_sync(FULL, act, sub + 16);
        float ov = __shfl_sync(FULL, act, sub + 24);
        cc = fmaf(fv, cc, iv * uv);
        h = ov * tanhap(cc);
    }

    // ---- final projection over 8 comps ----
    float p = h * __ldg(&w_fc[sub]);
    p += sx(p, 1);
    p += sx(p, 2);
    p += sx(p, 4);
    if (lane == 0 && ok) out[e] = p + __ldg(&b_fc[0]);
}

extern "C" void kernel_launch(void* const* d_in, const int* in_sizes, int n_in,
                              void* d_out, int out_size) {
    const float* x     = (const float*)d_in[0];
    const float* w_in  = (const float*)d_in[1];
    const float* b_in  = (const float*)d_in[2];
    const float* w_out = (const float*)d_in[3];
    const float* b_out = (const float*)d_in[4];
    const float* wq_f  = (const float*)d_in[5];
    const float* wq_i  = (const float*)d_in[6];
    const float* wq_u  = (const float*)d_in[7];
    const float* wq_o  = (const float*)d_in[8];
    const float* w_fc  = (const float*)d_in[9];
    const float* b_fc  = (const float*)d_in[10];

    int B = in_sizes[0] / (TT * 32);
    int blocks = (B + 7) / 8;              // 8 elements (warps) per block
    qlstmcf32b<<<blocks, 256>>>(x, w_in, b_in, w_out, b_out,
                                wq_f, wq_i, wq_u, wq_o, w_fc, b_fc,
                                (float*)d_out, B);
}

// round 15
// speedup vs baseline: 1.5389x; 1.1216x over previous
#include <cuda_runtime.h>

#define TT 64
#define FULL 0xffffffffu

__device__ __forceinline__ float sx(float v, int m) { return __shfl_xor_sync(FULL, v, m); }
__device__ __forceinline__ float tanhap(float v) {
    float r; asm("tanh.approx.f32 %0, %1;" : "=f"(r) : "f"(v)); return r;
}
// basis coefficient: factor p (0:cos(alpha),1:sin(alpha)), basis bit b (0->cY,1->sY)
__device__ __forceinline__ float fco(int p, int b, float cg, float sg) {
    return p ? (b ? cg : sg) : (b ? -sg : cg);
}

// 16 lanes per element, 2 elements per warp.
// lane = e2*16 + g*4 + c ; lane owns comps {2c, 2c+1} of gate g, wire c.
__global__ void __launch_bounds__(128)
qlstm16x2(const float* __restrict__ x,
          const float* __restrict__ w_in,  const float* __restrict__ b_in,
          const float* __restrict__ w_out, const float* __restrict__ b_out,
          const float* __restrict__ wq_f,  const float* __restrict__ wq_i,
          const float* __restrict__ wq_u,  const float* __restrict__ wq_o,
          const float* __restrict__ w_fc,  const float* __restrict__ b_fc,
          float* __restrict__ out, int B)
{
    const int lane   = threadIdx.x & 31;
    const int wib    = threadIdx.x >> 5;       // warp in block (0..3)
    const int e2     = lane >> 4;               // element half
    const int lane16 = lane & 15;
    const int g      = lane16 >> 2;
    const int c      = lane16 & 3;              // wire duty AND comp-pair index
    const int b16    = lane & ~15;
    const int b4     = lane & ~3;
    const int j0 = 2 * c, j1 = 2 * c + 1;
    const int slot = wib * 2 + e2;              // 0..7
    int e = blockIdx.x * 8 + slot;
    const bool ok = (e < B);
    if (!ok) e = B - 1;

    __shared__ float sxp[8][TT * 4 + 4];

    // ---- prepass: x-part of angles (incl. b_in); 4 timesteps per lane ----
    {
        const float* xe = x + (long)e * TT * 32;
        const int t0i = lane16 * 4;
        float acc[4][4];
#pragma unroll
        for (int i = 0; i < 4; ++i)
#pragma unroll
            for (int w = 0; w < 4; ++w) acc[i][w] = 0.f;
#pragma unroll
        for (int ch = 0; ch < 8; ++ch) {
            float4 wv[4];
#pragma unroll
            for (int w = 0; w < 4; ++w)
                wv[w] = *reinterpret_cast<const float4*>(&w_in[w * 40 + 8 + 4 * ch]);
#pragma unroll
            for (int i = 0; i < 4; ++i) {
                float4 xv = *reinterpret_cast<const float4*>(&xe[(t0i + i) * 32 + 4 * ch]);
#pragma unroll
                for (int w = 0; w < 4; ++w) {
                    acc[i][w] = fmaf(xv.x, wv[w].x, acc[i][w]);
                    acc[i][w] = fmaf(xv.y, wv[w].y, acc[i][w]);
                    acc[i][w] = fmaf(xv.z, wv[w].z, acc[i][w]);
                    acc[i][w] = fmaf(xv.w, wv[w].w, acc[i][w]);
                }
            }
        }
#pragma unroll
        for (int i = 0; i < 4; ++i)
#pragma unroll
            for (int w = 0; w < 4; ++w)
                sxp[slot][(t0i + i) * 4 + w] = acc[i][w] + __ldg(&b_in[w]);
    }
    __syncwarp();

    // ---- transpose-reduce weights: Whp[m][k] = W[(c^m)&3][2c+k] ----
    float Whp[4][2];
#pragma unroll
    for (int m = 0; m < 4; ++m) {
        Whp[m][0] = __ldg(&w_in[((c ^ m) & 3) * 40 + j0]);
        Whp[m][1] = __ldg(&w_in[((c ^ m) & 3) * 40 + j1]);
    }

    // ---- own-gate closed-form coefficient vectors for 2 comps ----
    const float* wq = (g == 0) ? wq_f : (g == 1) ? wq_i : (g == 2) ? wq_u : wq_o;
    float cb[4], sb[4], cg_[4], sg_[4];
#pragma unroll
    for (int w = 0; w < 4; ++w) {
        float bv = __ldg(&wq[4 + w]); cb[w] = cosf(bv); sb[w] = sinf(bv);
        float cv = __ldg(&wq[w]);     cg_[w] = cosf(cv); sg_[w] = sinf(cv);
    }
    const float asc = (g == 2) ? 1.f : 0.5f;

    float V013[2][8], V023[2][8], V13[2][4], V02[2][4], bo[2];
#pragma unroll
    for (int i = 0; i < 2; ++i) {
        const int comp = j0 + i;
        float Wo[4];
#pragma unroll
        for (int w = 0; w < 4; ++w) Wo[w] = asc * __ldg(&w_out[comp * 4 + w]);
        bo[i] = asc * __ldg(&b_out[comp]);

        {   // E0: wires {0,1,3}
            const int   p0[4] = {0, 7, 6, 1};
            const float K0[4] = {cb[1]*cb[2]*cb[3], cb[1]*cb[2]*sb[3],
                                 sb[1]*sb[2]*cb[3], sb[1]*sb[2]*sb[3]};
#pragma unroll
            for (int b = 0; b < 8; ++b) {
                float s = 0.f;
#pragma unroll
                for (int t = 0; t < 4; ++t)
                    s += K0[t] * fco(p0[t] & 1, b & 1, cg_[0], sg_[0])
                               * fco((p0[t] >> 1) & 1, (b >> 1) & 1, cg_[1], sg_[1])
                               * fco((p0[t] >> 2) & 1, (b >> 2) & 1, cg_[3], sg_[3]);
                V013[i][b] = Wo[0] * s;
            }
        }
        {   // E1: wires {0,2,3}
            const int   p1[2] = {0, 3};
            const float K1[2] = {cb[0]*cb[1], sb[0]*sb[1]};
#pragma unroll
            for (int b = 0; b < 8; ++b) {
                float s = 0.f;
#pragma unroll
                for (int t = 0; t < 2; ++t)
                    s += K1[t] * fco(p1[t] & 1, b & 1, cg_[0], sg_[0])
                               * fco((p1[t] >> 1) & 1, (b >> 1) & 1, cg_[2], sg_[2])
                               * fco((p1[t] >> 2) & 1, (b >> 2) & 1, cg_[3], sg_[3]);
                V023[i][b] = Wo[1] * s;
            }
        }
        {   // E2: wires {1,3}
            const int   p2[2] = {0, 3};
            const float K2[2] = {cb[0]*cb[1]*cb[2], cb[0]*sb[1]*sb[2]};
#pragma unroll
            for (int b = 0; b < 4; ++b) {
                float s = 0.f;
#pragma unroll
                for (int t = 0; t < 2; ++t)
                    s += K2[t] * fco(p2[t] & 1, b & 1, cg_[1], sg_[1])
                               * fco((p2[t] >> 1) & 1, (b >> 1) & 1, cg_[3], sg_[3]);
                V13[i][b] = Wo[2] * s;
            }
        }
        {   // E3: wires {0,2}
            const int   p3[4] = {0, 3, 2, 1};
            const float K3[4] = {cb[0]*cb[1]*cb[2]*cb[3], sb[0]*sb[1]*cb[2]*cb[3],
                                 sb[0]*cb[1]*sb[2]*sb[3], cb[0]*sb[1]*sb[2]*sb[3]};
#pragma unroll
            for (int b = 0; b < 4; ++b) {
                float s = 0.f;
#pragma unroll
                for (int t = 0; t < 4; ++t)
                    s += K3[t] * fco(p3[t] & 1, b & 1, cg_[0], sg_[0])
                               * fco((p3[t] >> 1) & 1, (b >> 1) & 1, cg_[2], sg_[2]);
                V02[i][b] = Wo[3] * s;
            }
        }
    }

    float cc0 = 0.f, cc1 = 0.f, h0 = 0.f, h1 = 0.f;

#pragma unroll 1
    for (int t = 0; t < TT; ++t) {
        // S1: angle transpose-reduce over 4 lanes (one stage)
        float xval = sxp[slot][t * 4 + c];
        float red = fmaf(h0, Whp[0][0], fmaf(h1, Whp[0][1], xval));
        red += sx(fmaf(h0, Whp[1][0], h1 * Whp[1][1]), 1);
        red += sx(fmaf(h0, Whp[2][0], h1 * Whp[2][1]), 2);
        red += sx(fmaf(h0, Whp[3][0], h1 * Whp[3][1]), 3);

        // S2: own sincos; share 4 wires within b4
        float mys, myc;
        __sincosf(red, &mys, &myc);
        float cY[4], sY[4];
#pragma unroll
        for (int w = 0; w < 4; ++w) {
            cY[w] = __shfl_sync(FULL, myc, b4 | w);
            sY[w] = __shfl_sync(FULL, mys, b4 | w);
        }

        // compact basis
        float p01[4] = {cY[0]*cY[1], sY[0]*cY[1], cY[0]*sY[1], sY[0]*sY[1]};
        float p02[4] = {cY[0]*cY[2], sY[0]*cY[2], cY[0]*sY[2], sY[0]*sY[2]};

        // two gate dots (own gate, comps j0/j1) with Y3 factored out
        float act0, act1;
#pragma unroll
        for (int i = 0; i < 2; ++i) {
            float a0 = V013[i][0] * p01[0], a1 = V013[i][1] * p01[1];
            a0 = fmaf(V013[i][2], p01[2], a0); a1 = fmaf(V013[i][3], p01[3], a1);
            a0 = fmaf(V023[i][0], p02[0], a0); a1 = fmaf(V023[i][1], p02[1], a1);
            a0 = fmaf(V023[i][2], p02[2], a0); a1 = fmaf(V023[i][3], p02[3], a1);
            a0 = fmaf(V13[i][0], cY[1], a0);   a1 = fmaf(V13[i][1], sY[1], a1);
            float A = a0 + a1;

            float b0 = V013[i][4] * p01[0], b1 = V013[i][5] * p01[1];
            b0 = fmaf(V013[i][6], p01[2], b0); b1 = fmaf(V013[i][7], p01[3], b1);
            b0 = fmaf(V023[i][4], p02[0], b0); b1 = fmaf(V023[i][5], p02[1], b1);
            b0 = fmaf(V023[i][6], p02[2], b0); b1 = fmaf(V023[i][7], p02[3], b1);
            b0 = fmaf(V13[i][2], cY[1], b0);   b1 = fmaf(V13[i][3], sY[1], b1);
            float Bv = b0 + b1;

            float g0 = fmaf(V02[i][0], p02[0], bo[i]);
            float g1 = V02[i][1] * p02[1];
            g0 = fmaf(V02[i][2], p02[2], g0);
            g1 = fmaf(V02[i][3], p02[3], g1);
            float gv = fmaf(cY[3], A, fmaf(sY[3], Bv, g0 + g1));

            float av = (g == 2) ? tanhap(gv) : fmaf(0.5f, tanhap(gv), 0.5f);
            if (i == 0) act0 = av; else act1 = av;
        }

        // S3: gather f,i,u,o for comps j0/j1 (within b16); cell update
        float fv0 = __shfl_sync(FULL, act0, b16 + c);
        float fv1 = __shfl_sync(FULL, act1, b16 + c);
        float iv0 = __shfl_sync(FULL, act0, b16 + 4 + c);
        float iv1 = __shfl_sync(FULL, act1, b16 + 4 + c);
        float uv0 = __shfl_sync(FULL, act0, b16 + 8 + c);
        float uv1 = __shfl_sync(FULL, act1, b16 + 8 + c);
        float ov0 = __shfl_sync(FULL, act0, b16 + 12 + c);
        float ov1 = __shfl_sync(FULL, act1, b16 + 12 + c);

        cc0 = fmaf(fv0, cc0, iv0 * uv0);
        cc1 = fmaf(fv1, cc1, iv1 * uv1);
        h0 = ov0 * tanhap(cc0);
        h1 = ov1 * tanhap(cc1);
    }

    // ---- final projection: sum over 4 lanes of a gate group ----
    float p = fmaf(h1, __ldg(&w_fc[j1]), h0 * __ldg(&w_fc[j0]));
    p += sx(p, 1);
    p += sx(p, 2);
    if (lane16 == 0 && ok) out[e] = p + __ldg(&b_fc[0]);
}

extern "C" void kernel_launch(void* const* d_in, const int* in_sizes, int n_in,
                              void* d_out, int out_size) {
    const float* x     = (const float*)d_in[0];
    const float* w_in  = (const float*)d_in[1];
    const float* b_in  = (const float*)d_in[2];
    const float* w_out = (const float*)d_in[3];
    const float* b_out = (const float*)d_in[4];
    const float* wq_f  = (const float*)d_in[5];
    const float* wq_i  = (const float*)d_in[6];
    const float* wq_u  = (const float*)d_in[7];
    const float* wq_o  = (const float*)d_in[8];
    const float* w_fc  = (const float*)d_in[9];
    const float* b_fc  = (const float*)d_in[10];

    int B = in_sizes[0] / (TT * 32);
    int blocks = (B + 7) / 8;              // 8 elements per 128-thread block
    qlstm16x2<<<blocks, 128>>>(x, w_in, b_in, w_out, b_out,
                               wq_f, wq_i, wq_u, wq_o, w_fc, b_fc,
                               (float*)d_out, B);
}